// round 16
// baseline (speedup 1.0000x reference)
#include <cuda_runtime.h>
#include <cuda_bf16.h>
#include <cstdint>
#include <cstddef>

#define CH   128
#define HH   96
#define WW   96
#define HW   9216          // 96*96
#define BATCH 16
#define NOUT 1000

// Padded mixed layout: data pixel (h,w) -> plane[(h+1)*PP + (w+2)]
#define PP    104
#define PPH   100
#define PLANE (PP * PPH)   // 10400 floats per (b,c) plane

// ---------------------------------------------------------------------------
// Scratch (device globals — no runtime allocation allowed)
// ---------------------------------------------------------------------------
__device__ float g_mixedA[(size_t)BATCH * CH * PLANE];  // 85.2 MB (padded)
__device__ float g_mixedB[(size_t)BATCH * CH * PLANE];  // 85.2 MB (padded)
__device__ float g_x[(size_t)BATCH * CH * HW];          // 75.5 MB
__device__ float g_pool[BATCH * CH];
// A fragments in mma register order: [slot][kstep(8)][mtile(8)][lane(32)]
__device__ uint4 g_afh[5 * 8 * 8 * 32];
__device__ uint4 g_afl[5 * 8 * 8 * 32];

// ---------------------------------------------------------------------------
__device__ __forceinline__ unsigned short bfbits(float x) {
    return __bfloat16_as_ushort(__float2bfloat16_rn(x));
}
__device__ __forceinline__ float bfval(float x) {
    return __bfloat162float(__float2bfloat16_rn(x));
}
__device__ __forceinline__ unsigned int pack2(unsigned short lo, unsigned short hi) {
    return (unsigned int)lo | ((unsigned int)hi << 16);
}
__device__ __forceinline__ void mma_bf16(float* d, uint4 a,
                                         unsigned int b0, unsigned int b1) {
    asm volatile(
        "mma.sync.aligned.m16n8k16.row.col.f32.bf16.bf16.f32 "
        "{%0,%1,%2,%3}, {%4,%5,%6,%7}, {%8,%9}, {%0,%1,%2,%3};"
        : "+f"(d[0]), "+f"(d[1]), "+f"(d[2]), "+f"(d[3])
        : "r"(a.x), "r"(a.y), "r"(a.z), "r"(a.w), "r"(b0), "r"(b1));
}

// ---------------------------------------------------------------------------
// prep_all: merged border-zero (blocks < 4096) + A-fragment packing + pool
// zero (blocks >= 4096). 128 threads per block.
// ---------------------------------------------------------------------------
__global__ void prep_all(const float* __restrict__ in_lin,
                         const float* __restrict__ lay_lin,
                         float* __restrict__ pool,
                         float* __restrict__ mA,
                         float* __restrict__ mB) {
    if (blockIdx.x < 4096) {
        // border zeroing for both padded mixed buffers
        float* pl = ((blockIdx.x & 1) ? mB : mA) + (size_t)(blockIdx.x >> 1) * PLANE;
        for (int i = threadIdx.x; i < 4 * PP + 4 * 96; i += 128) {
            int idx;
            if (i < 4 * PP) {
                int r4 = i / PP;
                int rr = (r4 == 0) ? 0 : (96 + r4);
                idx = rr * PP + (i - r4 * PP);
            } else {
                int j  = i - 4 * PP;
                int c4 = j / 96;
                int col = (c4 < 2) ? c4 : (96 + c4);
                idx = (1 + (j - c4 * 96)) * PP + col;
            }
            pl[idx] = 0.f;
        }
        return;
    }

    int t = (blockIdx.x - 4096) * 128 + threadIdx.x;
    if (t < BATCH * CH) pool[t] = 0.f;

    const float* lin;
    int slot, K, local;
    if (t < 1024) {
        slot = 0; K = 64; local = t; lin = in_lin;
    } else if (t < 1024 + 4 * 2048) {
        int j = t - 1024;
        slot = 1 + j / 2048; K = 128; local = j & 2047;
        lin = lay_lin + (size_t)(slot - 1) * CH * CH;
    } else return;

    int lane  = local & 31;
    int mtile = (local >> 5) & 7;
    int ks    = local >> 8;
    int m0 = mtile * 16 + (lane >> 2);
    int k0 = ks * 16 + (lane & 3) * 2;

    float a00 = lin[(size_t)m0 * K + k0],           a01 = lin[(size_t)m0 * K + k0 + 1];
    float a10 = lin[(size_t)(m0 + 8) * K + k0],     a11 = lin[(size_t)(m0 + 8) * K + k0 + 1];
    float a02 = lin[(size_t)m0 * K + k0 + 8],       a03 = lin[(size_t)m0 * K + k0 + 9];
    float a12 = lin[(size_t)(m0 + 8) * K + k0 + 8], a13 = lin[(size_t)(m0 + 8) * K + k0 + 9];

    uint4 h, l;
    h.x = pack2(bfbits(a00), bfbits(a01));
    h.y = pack2(bfbits(a10), bfbits(a11));
    h.z = pack2(bfbits(a02), bfbits(a03));
    h.w = pack2(bfbits(a12), bfbits(a13));
    l.x = pack2(bfbits(a00 - bfval(a00)), bfbits(a01 - bfval(a01)));
    l.y = pack2(bfbits(a10 - bfval(a10)), bfbits(a11 - bfval(a11)));
    l.z = pack2(bfbits(a02 - bfval(a02)), bfbits(a03 - bfval(a03)));
    l.w = pack2(bfbits(a12 - bfval(a12)), bfbits(a13 - bfval(a13)));

    int off = ((slot * 8 + ks) * 8 + mtile) * 32 + lane;
    g_afh[off] = h;
    g_afl[off] = l;
}

// ---------------------------------------------------------------------------
// GEMM mainloop + padded epilogue (R13/R14 proven).
// ---------------------------------------------------------------------------
#define BPITCH 136
template<int K>
__device__ __forceinline__ void gemm_core(const unsigned int* Bh,
                                          const unsigned int* Bl,
                                          float* outp, int b, int pbase,
                                          int slot, int lane, int warp) {
    constexpr int KS = K / 16;
    const int wm = warp >> 2;
    const int wn = warp & 3;

    float acc[4][4][4];
#pragma unroll
    for (int t = 0; t < 4; t++)
#pragma unroll
        for (int u = 0; u < 4; u++)
#pragma unroll
            for (int r = 0; r < 4; r++) acc[t][u][r] = 0.f;

    const uint4* afh = g_afh + (size_t)slot * 8 * 8 * 32;
    const uint4* afl = g_afl + (size_t)slot * 8 * 8 * 32;

#pragma unroll
    for (int ks = 0; ks < KS; ks++) {
        unsigned int bh0[4], bh1[4], bl0[4], bl1[4];
        const int r0 = (ks * 8 + (lane & 3)) * BPITCH;
        const int r1 = r0 + 4 * BPITCH;
#pragma unroll
        for (int u = 0; u < 4; u++) {
            int n = wn * 32 + u * 8 + (lane >> 2);
            bh0[u] = Bh[r0 + n]; bh1[u] = Bh[r1 + n];
            bl0[u] = Bl[r0 + n]; bl1[u] = Bl[r1 + n];
        }
#pragma unroll
        for (int t = 0; t < 4; t++) {
            uint4 ah = afh[(ks * 8 + wm * 4 + t) * 32 + lane];
            uint4 al = afl[(ks * 8 + wm * 4 + t) * 32 + lane];
#pragma unroll
            for (int u = 0; u < 4; u++) {
                mma_bf16(acc[t][u], ah, bh0[u], bh1[u]);
                mma_bf16(acc[t][u], ah, bl0[u], bl1[u]);
                mma_bf16(acc[t][u], al, bh0[u], bh1[u]);
            }
        }
    }

    float* mb = outp + (size_t)b * CH * PLANE;
#pragma unroll
    for (int t = 0; t < 4; t++) {
        int m0 = wm * 64 + t * 16 + (lane >> 2);
#pragma unroll
        for (int u = 0; u < 4; u++) {
            int p = pbase + wn * 32 + u * 8 + (lane & 3) * 2;
            int h = p / 96;
            int w = p - h * 96;
            size_t po = (size_t)(h + 1) * PP + (w + 2);
            *(float2*)(mb + (size_t)m0 * PLANE + po)       = make_float2(acc[t][u][0], acc[t][u][1]);
            *(float2*)(mb + (size_t)(m0 + 8) * PLANE + po) = make_float2(acc[t][u][2], acc[t][u][3]);
        }
    }
}

// ---------------------------------------------------------------------------
// gemm0: input layer (K=64), reads fp32 x directly.
// ---------------------------------------------------------------------------
template<int K>
__global__ __launch_bounds__(256, 2)
void mix_gemm_mma(const float* __restrict__ xin,
                  float* __restrict__ outp, int slot) {
    constexpr int K2 = K / 2;
    extern __shared__ unsigned int smb[];
    unsigned int* Bh = smb;
    unsigned int* Bl = smb + K2 * BPITCH;

    const int b     = blockIdx.y;
    const int pbase = blockIdx.x * 128;
    const int tid   = threadIdx.x;

    {
        const float* xb = xin + (size_t)b * K * HW + pbase;
        for (int i = tid; i < K2 * 128; i += 256) {
            int k2 = i >> 7, p = i & 127;
            float v0 = xb[(size_t)(2 * k2) * HW + p];
            float v1 = xb[(size_t)(2 * k2 + 1) * HW + p];
            unsigned short h0 = bfbits(v0), h1 = bfbits(v1);
            Bh[k2 * BPITCH + p] = pack2(h0, h1);
            Bl[k2 * BPITCH + p] = pack2(
                bfbits(v0 - __bfloat162float(__ushort_as_bfloat16(h0))),
                bfbits(v1 - __bfloat162float(__ushort_as_bfloat16(h1))));
        }
    }
    __syncthreads();
    gemm_core<K>(Bh, Bl, outp, b, pbase, slot, tid & 31, tid >> 5);
}

// ---------------------------------------------------------------------------
// Fused kernel: sample all 128 channels for this block's 128 pixels (warp =
// 16 channels, channel PAIRS, unroll 2 -> 4 channels / 16 taps in flight),
// residual add, fp32 x write, pair-packed bf16 into smem B tile -> GEMM.
// ---------------------------------------------------------------------------
__global__ __launch_bounds__(256, 2)
void fused_sample_gemm(const float* __restrict__ mixin,
                       float* __restrict__ mixout,
                       const float* __restrict__ geo,
                       const float* __restrict__ box,
                       const float* __restrict__ resid,   // null for layer 0
                       float* __restrict__ xout,
                       int slot) {
    extern __shared__ unsigned int smb[];
    unsigned int* Bh = smb;
    unsigned int* Bl = smb + 64 * BPITCH;

    const int b     = blockIdx.y;
    const int pbase = blockIdx.x * 128;
    const int tid   = threadIdx.x;
    const int lane  = tid & 31;
    const int warp  = tid >> 5;

    // hoisted per-pixel-group normalized coords (invariant across channels)
    float gxcv[4], gycv[4];
#pragma unroll
    for (int pg = 0; pg < 4; pg++) {
        int p = pbase + pg * 32 + lane;
        int h = p / 96;
        int w = p - h * 96;
        gxcv[pg] = (w + 0.5f) * (2.0f / WW) - 1.0f;
        gycv[pg] = (h + 0.5f) * (2.0f / HH) - 1.0f;
    }

    // ---- sample phase: 8 channel-pair iterations per warp, unrolled 2x ----
#pragma unroll 2
    for (int cj = 0; cj < 8; cj++) {
        const int c0 = warp * 16 + cj * 2;     // even channel; pair (c0, c0+1)
        const float* gA = geo + c0 * 6;
        const float* gB = gA + 6;
        const float a0 = __ldg(gA + 0), a1 = __ldg(gA + 1), a2 = __ldg(gA + 2);
        const float a3 = __ldg(gA + 3), a4 = __ldg(gA + 4), a5 = __ldg(gA + 5);
        const float b0 = __ldg(gB + 0), b1 = __ldg(gB + 1), b2 = __ldg(gB + 2);
        const float b3 = __ldg(gB + 3), b4 = __ldg(gB + 4), b5 = __ldg(gB + 5);
        const float* qA = box + c0 * 6;
        const float* qB = qA + 6;
        const float pa0 = __ldg(qA + 0), pa1 = __ldg(qA + 1), pa2 = __ldg(qA + 2);
        const float pa3 = __ldg(qA + 3), pa4 = __ldg(qA + 4), pa5 = __ldg(qA + 5);
        const float pb0 = __ldg(qB + 0), pb1 = __ldg(qB + 1), pb2 = __ldg(qB + 2);
        const float pb3 = __ldg(qB + 3), pb4 = __ldg(qB + 4), pb5 = __ldg(qB + 5);

        const float* plA = mixin + ((size_t)b * CH + c0) * PLANE;
        const float* plB = plA + PLANE;
        const int k2 = c0 >> 1;

#pragma unroll
        for (int pg = 0; pg < 4; pg++) {
            const int pl = pg * 32 + lane;
            const float gxc = gxcv[pg], gyc = gycv[pg];

            float ixA = (a0 * gxc + a1 * gyc + a2) * 48.f + 47.5f;
            float iyA = (a3 * gxc + a4 * gyc + a5) * 48.f + 47.5f;
            ixA = fminf(fmaxf(ixA, -1.0f), 96.0f);
            iyA = fminf(fmaxf(iyA, -1.0f), 96.0f);
            float fxA = floorf(ixA), fyA = floorf(iyA);
            const float* tA = plA + (size_t)((int)fyA + 1) * PP + ((int)fxA + 2);
            float ixB = (b0 * gxc + b1 * gyc + b2) * 48.f + 47.5f;
            float iyB = (b3 * gxc + b4 * gyc + b5) * 48.f + 47.5f;
            ixB = fminf(fmaxf(ixB, -1.0f), 96.0f);
            iyB = fminf(fmaxf(iyB, -1.0f), 96.0f);
            float fxB = floorf(ixB), fyB = floorf(iyB);
            const float* tB = plB + (size_t)((int)fyB + 1) * PP + ((int)fxB + 2);

            float tA00 = tA[0],  tA01 = tA[1],  tA10 = tA[PP], tA11 = tA[PP + 1];
            float tB00 = tB[0],  tB01 = tB[1],  tB10 = tB[PP], tB11 = tB[PP + 1];

            float wxA1 = ixA - fxA, wyA1 = iyA - fyA;
            float wxA0 = 1.f - wxA1, wyA0 = 1.f - wyA1;
            float sA = wyA0 * fmaf(wxA0, tA00, wxA1 * tA01)
                     + wyA1 * fmaf(wxA0, tA10, wxA1 * tA11);
            float wxB1 = ixB - fxB, wyB1 = iyB - fyB;
            float wxB0 = 1.f - wxB1, wyB0 = 1.f - wyB1;
            float sB = wyB0 * fmaf(wxB0, tB00, wxB1 * tB01)
                     + wyB1 * fmaf(wxB0, tB10, wxB1 * tB11);

            float bixA = (pa0 * gxc + pa1 * gyc + pa2) * 48.f + 47.5f;
            float biyA = (pa3 * gxc + pa4 * gyc + pa5) * 48.f + 47.5f;
            float bfxA = floorf(bixA), bfyA = floorf(biyA);
            int   bxA = (int)bfxA, byA = (int)bfyA;
            float bwxA = bixA - bfxA, bwyA = biyA - bfyA;
            float sxA = (((unsigned)bxA       < (unsigned)WW) ? (1.f - bwxA) : 0.f)
                      + (((unsigned)(bxA + 1) < (unsigned)WW) ? bwxA         : 0.f);
            float syA = (((unsigned)byA       < (unsigned)HH) ? (1.f - bwyA) : 0.f)
                      + (((unsigned)(byA + 1) < (unsigned)HH) ? bwyA         : 0.f);
            float bixB = (pb0 * gxc + pb1 * gyc + pb2) * 48.f + 47.5f;
            float biyB = (pb3 * gxc + pb4 * gyc + pb5) * 48.f + 47.5f;
            float bfxB = floorf(bixB), bfyB = floorf(biyB);
            int   bxB = (int)bfxB, byB = (int)bfyB;
            float bwxB = bixB - bfxB, bwyB = biyB - bfyB;
            float sxB = (((unsigned)bxB       < (unsigned)WW) ? (1.f - bwxB) : 0.f)
                      + (((unsigned)(bxB + 1) < (unsigned)WW) ? bwxB         : 0.f);
            float syB = (((unsigned)byB       < (unsigned)HH) ? (1.f - bwyB) : 0.f)
                      + (((unsigned)(byB + 1) < (unsigned)HH) ? bwyB         : 0.f);

            float vA = sA * (sxA * syA);
            float vB = sB * (sxB * syB);

            const size_t idxA = ((size_t)b * CH + c0) * HW + pbase + pl;
            if (resid) {
                vA += resid[idxA];
                vB += resid[idxA + HW];
            }
            xout[idxA]      = vA;
            xout[idxA + HW] = vB;

            unsigned short hA = bfbits(vA);
            unsigned short lA = bfbits(vA - __bfloat162float(__ushort_as_bfloat16(hA)));
            unsigned short hB = bfbits(vB);
            unsigned short lB = bfbits(vB - __bfloat162float(__ushort_as_bfloat16(hB)));
            Bh[k2 * BPITCH + pl] = pack2(hA, hB);
            Bl[k2 * BPITCH + pl] = pack2(lA, lB);
        }
    }
    __syncthreads();

    // ---- GEMM phase ----
    gemm_core<128>(Bh, Bl, mixout, b, pbase, slot, lane, warp);
}

// ---------------------------------------------------------------------------
// Final standalone sample (R13 proven): feat write + fused pool.
// ---------------------------------------------------------------------------
__global__ void sample_kernel(const float* __restrict__ mixedp,
                              const float* __restrict__ geo,
                              const float* __restrict__ box,
                              const float* __restrict__ resid,
                              float* __restrict__ out,
                              float* __restrict__ pool) {
    const int c = blockIdx.y;
    const int b = blockIdx.z;
    const int p = blockIdx.x * 256 + threadIdx.x;
    const int h = p / WW;
    const int w = p - h * WW;

    const float gxc = (w + 0.5f) * (2.0f / WW) - 1.0f;
    const float gyc = (h + 0.5f) * (2.0f / HH) - 1.0f;

    const float* g = geo + c * 6;
    float ix = (__ldg(g + 0) * gxc + __ldg(g + 1) * gyc + __ldg(g + 2)) * 48.f + 47.5f;
    float iy = (__ldg(g + 3) * gxc + __ldg(g + 4) * gyc + __ldg(g + 5)) * 48.f + 47.5f;
    ix = fminf(fmaxf(ix, -1.0f), 96.0f);
    iy = fminf(fmaxf(iy, -1.0f), 96.0f);
    float fx0 = floorf(ix), fy0 = floorf(iy);
    int   x0 = (int)fx0, y0 = (int)fy0;
    float wx1 = ix - fx0, wy1 = iy - fy0;
    float wx0 = 1.0f - wx1, wy0 = 1.0f - wy1;

    const float* tapb = mixedp + ((size_t)b * CH + c) * PLANE
                      + (size_t)(y0 + 1) * PP + (x0 + 2);
    float t00 = tapb[0],  t01 = tapb[1];
    float t10 = tapb[PP], t11 = tapb[PP + 1];
    float s = wy0 * fmaf(wx0, t00, wx1 * t01)
            + wy1 * fmaf(wx0, t10, wx1 * t11);

    const float* bx = box + c * 6;
    float bix = (__ldg(bx + 0) * gxc + __ldg(bx + 1) * gyc + __ldg(bx + 2)) * 48.f + 47.5f;
    float biy = (__ldg(bx + 3) * gxc + __ldg(bx + 4) * gyc + __ldg(bx + 5)) * 48.f + 47.5f;
    float bfx0 = floorf(bix), bfy0 = floorf(biy);
    int   bx0 = (int)bfx0, by0 = (int)bfy0;
    float bwx1 = bix - bfx0, bwy1 = biy - bfy0;
    float sx = (((unsigned)bx0       < (unsigned)WW) ? (1.f - bwx1) : 0.f)
             + (((unsigned)(bx0 + 1) < (unsigned)WW) ? bwx1         : 0.f);
    float sy = (((unsigned)by0       < (unsigned)HH) ? (1.f - bwy1) : 0.f)
             + (((unsigned)(by0 + 1) < (unsigned)HH) ? bwy1         : 0.f);

    const size_t idx = ((size_t)b * CH + c) * HW + p;
    float v = s * (sx * sy);
    if (resid) v += resid[idx];
    out[idx] = v;

    float r = v;
    for (int o = 16; o > 0; o >>= 1) r += __shfl_down_sync(0xffffffffu, r, o);
    __shared__ float sm[8];
    if ((threadIdx.x & 31) == 0) sm[threadIdx.x >> 5] = r;
    __syncthreads();
    if (threadIdx.x == 0) {
        float tt = 0.f;
        for (int i = 0; i < 8; i++) tt += sm[i];
        atomicAdd(pool + b * CH + c, tt);
    }
}

// ---------------------------------------------------------------------------
__global__ void dense_kernel(const float* __restrict__ pooled,
                             const float* __restrict__ dw,
                             const float* __restrict__ db,
                             float* __restrict__ logits) {
    int gid = blockIdx.x * 256 + threadIdx.x;
    if (gid >= BATCH * NOUT) return;
    int o = gid % NOUT;
    int b = gid / NOUT;
    const float* pr = pooled + b * CH;
    const float* wr = dw + (size_t)o * CH;
    float s = 0.f;
#pragma unroll 16
    for (int c = 0; c < CH; c++) s = fmaf(pr[c], wr[c], s);
    logits[gid] = s * (1.0f / HW) + db[o];
}

// ---------------------------------------------------------------------------
extern "C" void kernel_launch(void* const* d_in, const int* in_sizes, int n_in,
                              void* d_out, int out_size) {
    const float* x       = (const float*)d_in[0];
    const float* in_geo  = (const float*)d_in[1];
    const float* in_box  = (const float*)d_in[2];
    const float* in_lin  = (const float*)d_in[3];
    const float* lay_geo = (const float*)d_in[4];
    const float* lay_box = (const float*)d_in[5];
    const float* lay_lin = (const float*)d_in[6];
    const float* dense_w = (const float*)d_in[7];
    const float* dense_b = (const float*)d_in[8];

    float* out    = (float*)d_out;
    float* logits = out;
    float* feat   = out + BATCH * NOUT;

    float *mA, *mB, *x_p, *pool_p;
    cudaGetSymbolAddress((void**)&mA,     g_mixedA);
    cudaGetSymbolAddress((void**)&mB,     g_mixedB);
    cudaGetSymbolAddress((void**)&x_p,    g_x);
    cudaGetSymbolAddress((void**)&pool_p, g_pool);

    const int smem64  = 2 * 32 * BPITCH * 4;   // 34816
    const int smem128 = 2 * 64 * BPITCH * 4;   // 69632
    cudaFuncSetAttribute(mix_gemm_mma<64>, cudaFuncAttributeMaxDynamicSharedMemorySize, smem64);
    cudaFuncSetAttribute(fused_sample_gemm, cudaFuncAttributeMaxDynamicSharedMemorySize, smem128);

    // merged prep: borders + A fragments + pool zero (single launch)
    prep_all<<<4096 + 72, 128>>>(in_lin, lay_lin, pool_p, mA, mB);

    dim3 ggrid(HW / 128, BATCH);          // (72, 16)
    dim3 sgrid(HW / 256, CH, BATCH);      // (36, 128, 16)

    // gemm0: mixedA = in_lin @ x_raw
    mix_gemm_mma<64><<<ggrid, 256, smem64>>>(x, mA, 0);

    // F0: x1 = sample(mixedA; in_geo/in_box), mixedB = lay_lin0 @ x1
    fused_sample_gemm<<<ggrid, 256, smem128>>>(mA, mB, in_geo, in_box,
                                               nullptr, x_p, 1);
    // F1..F3
    fused_sample_gemm<<<ggrid, 256, smem128>>>(mB, mA,
        lay_geo + 0 * CH * 6, lay_box + 0 * CH * 6, x_p, x_p, 2);
    fused_sample_gemm<<<ggrid, 256, smem128>>>(mA, mB,
        lay_geo + 1 * CH * 6, lay_box + 1 * CH * 6, x_p, x_p, 3);
    fused_sample_gemm<<<ggrid, 256, smem128>>>(mB, mA,
        lay_geo + 2 * CH * 6, lay_box + 2 * CH * 6, x_p, x_p, 4);

    // final sample: feat = sample(mixedA; lay_geo[3]) + x4, fused pool
    sample_kernel<<<sgrid, 256>>>(mA, lay_geo + 3 * CH * 6,
                                  lay_box + 3 * CH * 6, x_p, feat, pool_p);

    dense_kernel<<<(BATCH * NOUT + 255) / 256, 256>>>(pool_p, dense_w, dense_b, logits);
}